// round 12
// baseline (speedup 1.0000x reference)
#include <cuda_runtime.h>
#include <cuda_fp16.h>
#include <cstdint>

#define D 512
#define ROW_U4 64         // uint4 per fp16 row (512*2B/16B)
#define MAX_NODES 100000
#define MAX_E 2000000
#define SCAN_TILE 1024
#define MAX_SCAN_BLOCKS 128

// fp16 copies (uint4-typed for alignment)
__device__ uint4 g_h2[(size_t)MAX_NODES * ROW_U4];     // h in fp16
__device__ uint4 g_agg_h[(size_t)MAX_NODES * ROW_U4];  // agg in fp16 (GEMM A)
__device__ uint4 g_wt_h[(size_t)D * D / 8];            // W^T fp16 [N][K]
__device__ int g_is64;
// CSR-by-dst structures
__device__ int   g_cnt[MAX_NODES];
__device__ int   g_off[MAX_NODES + 1];
__device__ int   g_cur[MAX_NODES];
__device__ int2  g_edge[MAX_E];   // (src, edge_weight bits) combined
__device__ int   g_bsum[MAX_SCAN_BLOCKS];

// Bit-cast helpers
__device__ __forceinline__ unsigned h2_to_u(__half2 h) {
    return *reinterpret_cast<unsigned*>(&h);
}
__device__ __forceinline__ __half2 u_to_h2(unsigned u) {
    return *reinterpret_cast<__half2*>(&u);
}
__device__ __forceinline__ void ldsm_x4(unsigned& r0, unsigned& r1,
                                        unsigned& r2, unsigned& r3,
                                        uint32_t addr) {
    asm volatile(
        "ldmatrix.sync.aligned.m8n8.x4.shared.b16 {%0,%1,%2,%3}, [%4];"
        : "=r"(r0), "=r"(r1), "=r"(r2), "=r"(r3) : "r"(addr));
}
__device__ __forceinline__ void cp_async16(uint32_t dst_smem, const void* src,
                                           int src_size) {
    asm volatile("cp.async.cg.shared.global [%0], [%1], 16, %2;"
                 :: "r"(dst_smem), "l"(src), "r"(src_size) : "memory");
}
__device__ __forceinline__ void cp_commit() {
    asm volatile("cp.async.commit_group;" ::: "memory");
}
__device__ __forceinline__ void cp_wait0() {
    asm volatile("cp.async.wait_group 0;" ::: "memory");
}

// ---------------------------------------------------------------------------
__global__ void detect_idx_dtype(const unsigned* __restrict__ src_words) {
    int all_zero = 1;
    for (int i = 1; i < 64; i += 2)
        if (src_words[i] != 0u) all_zero = 0;
    g_is64 = all_zero;
}

__global__ void convert_h(const float* __restrict__ h, long long n_u4) {
    long long i = blockIdx.x * (long long)blockDim.x + threadIdx.x;
    long long stride = gridDim.x * (long long)blockDim.x;
    for (; i < n_u4; i += stride) {
        const float4* p = reinterpret_cast<const float4*>(h + i * 8);
        float4 v0 = p[0], v1 = p[1];
        uint4 o;
        o.x = h2_to_u(__floats2half2_rn(v0.x, v0.y));
        o.y = h2_to_u(__floats2half2_rn(v0.z, v0.w));
        o.z = h2_to_u(__floats2half2_rn(v1.x, v1.y));
        o.w = h2_to_u(__floats2half2_rn(v1.z, v1.w));
        g_h2[i] = o;
    }
}

__global__ void transpose_w_h(const float* __restrict__ W) {
    __shared__ float t[32][33];
    int bx = blockIdx.x * 32, by = blockIdx.y * 32;
    t[threadIdx.y][threadIdx.x] = W[(by + threadIdx.y) * D + bx + threadIdx.x];
    __syncthreads();
    __half* wt = reinterpret_cast<__half*>(g_wt_h);
    wt[(size_t)(bx + threadIdx.y) * D + by + threadIdx.x] =
        __float2half_rn(t[threadIdx.x][threadIdx.y]);
}

__global__ void zero_cnt(int M) {
    int i = blockIdx.x * blockDim.x + threadIdx.x;
    if (i < M) g_cnt[i] = 0;
}

__global__ void hist_dst(const void* __restrict__ dst_raw, int E) {
    int e = blockIdx.x * blockDim.x + threadIdx.x;
    if (e >= E) return;
    int d = g_is64 ? (int)reinterpret_cast<const long long*>(dst_raw)[e]
                   : reinterpret_cast<const int*>(dst_raw)[e];
    atomicAdd(&g_cnt[d], 1);
}

__global__ void scan_phase1(int M) {
    __shared__ int wsum[32];
    const int tid = threadIdx.x, lane = tid & 31, wid = tid >> 5;
    const int gi = blockIdx.x * SCAN_TILE + tid;

    int x = (gi < M) ? g_cnt[gi] : 0;

    int v = x;
#pragma unroll
    for (int d = 1; d < 32; d <<= 1) {
        int t = __shfl_up_sync(0xffffffffu, v, d);
        if (lane >= d) v += t;
    }
    if (lane == 31) wsum[wid] = v;
    __syncthreads();
    if (wid == 0) {
        int w = wsum[lane];
#pragma unroll
        for (int d = 1; d < 32; d <<= 1) {
            int t = __shfl_up_sync(0xffffffffu, w, d);
            if (lane >= d) w += t;
        }
        wsum[lane] = w;
    }
    __syncthreads();

    int excl = (v - x) + (wid > 0 ? wsum[wid - 1] : 0);
    if (gi < M) g_off[gi] = excl;
    if (tid == SCAN_TILE - 1) g_bsum[blockIdx.x] = excl + x;
}

__global__ void scan_phase2(int nblocks) {
    const int lane = threadIdx.x;
    int run = 0;
    for (int base = 0; base < nblocks; base += 32) {
        int i = base + lane;
        int x = (i < nblocks) ? g_bsum[i] : 0;
        int v = x;
#pragma unroll
        for (int d = 1; d < 32; d <<= 1) {
            int t = __shfl_up_sync(0xffffffffu, v, d);
            if (lane >= d) v += t;
        }
        if (i < nblocks) g_bsum[i] = run + (v - x);
        run += __shfl_sync(0xffffffffu, v, 31);
    }
}

__global__ void scan_phase3(int M, int E) {
    const int gi = blockIdx.x * SCAN_TILE + threadIdx.x;
    if (gi < M) {
        int o = g_off[gi] + g_bsum[blockIdx.x];
        g_off[gi] = o;
        g_cur[gi] = o;
    }
    if (gi == 0) g_off[M] = E;
}

__global__ void reorder_edges(const void* __restrict__ src_raw,
                              const void* __restrict__ dst_raw,
                              const float* __restrict__ ew, int E) {
    int e = blockIdx.x * blockDim.x + threadIdx.x;
    if (e >= E) return;
    int s, d;
    if (g_is64) {
        s = (int)reinterpret_cast<const long long*>(src_raw)[e];
        d = (int)reinterpret_cast<const long long*>(dst_raw)[e];
    } else {
        s = reinterpret_cast<const int*>(src_raw)[e];
        d = reinterpret_cast<const int*>(dst_raw)[e];
    }
    int pos = atomicAdd(&g_cur[d], 1);
    g_edge[pos] = make_int2(s, __float_as_int(ew[e]));
}

// ---------------------------------------------------------------------------
// Gather (fp16 rows): one warp per dst node, 4-edge unroll (16 LDG in flight).
// ---------------------------------------------------------------------------
__device__ __forceinline__ void acc_u4(float2* acc, uint4 q, float w, int base) {
    float2 f;
    f = __half22float2(u_to_h2(q.x));
    acc[base + 0].x += f.x * w; acc[base + 0].y += f.y * w;
    f = __half22float2(u_to_h2(q.y));
    acc[base + 1].x += f.x * w; acc[base + 1].y += f.y * w;
    f = __half22float2(u_to_h2(q.z));
    acc[base + 2].x += f.x * w; acc[base + 2].y += f.y * w;
    f = __half22float2(u_to_h2(q.w));
    acc[base + 3].x += f.x * w; acc[base + 3].y += f.y * w;
}

__global__ void gather_agg(int M) {
    int node = (int)((blockIdx.x * (unsigned)blockDim.x + threadIdx.x) >> 5);
    if (node >= M) return;
    const int lane = threadIdx.x & 31;
    const int beg = g_off[node];
    const int end = g_off[node + 1];

    float2 acc[8];
#pragma unroll
    for (int i = 0; i < 8; i++) acc[i] = make_float2(0.f, 0.f);

    int e = beg;
    for (; e + 3 < end; e += 4) {
        int2 e0 = g_edge[e],     e1 = g_edge[e + 1];
        int2 e2 = g_edge[e + 2], e3 = g_edge[e + 3];
        float w0 = __int_as_float(e0.y), w1 = __int_as_float(e1.y);
        float w2 = __int_as_float(e2.y), w3 = __int_as_float(e3.y);
        const uint4* p0 = g_h2 + (size_t)e0.x * ROW_U4 + lane * 2;
        const uint4* p1 = g_h2 + (size_t)e1.x * ROW_U4 + lane * 2;
        const uint4* p2 = g_h2 + (size_t)e2.x * ROW_U4 + lane * 2;
        const uint4* p3 = g_h2 + (size_t)e3.x * ROW_U4 + lane * 2;
        uint4 q00 = p0[0], q01 = p0[1];
        uint4 q10 = p1[0], q11 = p1[1];
        uint4 q20 = p2[0], q21 = p2[1];
        uint4 q30 = p3[0], q31 = p3[1];
        acc_u4(acc, q00, w0, 0); acc_u4(acc, q01, w0, 4);
        acc_u4(acc, q10, w1, 0); acc_u4(acc, q11, w1, 4);
        acc_u4(acc, q20, w2, 0); acc_u4(acc, q21, w2, 4);
        acc_u4(acc, q30, w3, 0); acc_u4(acc, q31, w3, 4);
    }
    for (; e < end; e++) {
        int2 e0 = g_edge[e];
        float w0 = __int_as_float(e0.y);
        const uint4* p0 = g_h2 + (size_t)e0.x * ROW_U4 + lane * 2;
        uint4 q00 = p0[0], q01 = p0[1];
        acc_u4(acc, q00, w0, 0); acc_u4(acc, q01, w0, 4);
    }

    uint4 o0, o1;
    o0.x = h2_to_u(__floats2half2_rn(acc[0].x, acc[0].y));
    o0.y = h2_to_u(__floats2half2_rn(acc[1].x, acc[1].y));
    o0.z = h2_to_u(__floats2half2_rn(acc[2].x, acc[2].y));
    o0.w = h2_to_u(__floats2half2_rn(acc[3].x, acc[3].y));
    o1.x = h2_to_u(__floats2half2_rn(acc[4].x, acc[4].y));
    o1.y = h2_to_u(__floats2half2_rn(acc[5].x, acc[5].y));
    o1.z = h2_to_u(__floats2half2_rn(acc[6].x, acc[6].y));
    o1.w = h2_to_u(__floats2half2_rn(acc[7].x, acc[7].y));
    uint4* o = g_agg_h + (size_t)node * ROW_U4 + lane * 2;
    o[0] = o0; o[1] = o1;
}

// ---------------------------------------------------------------------------
// fp16 mma.sync GEMM, double-buffered smem with cp.async tile staging.
// Block tile 128x256, BK=32, warp tile 64x64, m16n8k16, ldmatrix.x4.
// ---------------------------------------------------------------------------
#define BM 128
#define BN 256
#define BK 32
#define HS 20   // half2 stride per row
#define ABUF (BM * HS)
#define BBUF (BN * HS)

__global__ __launch_bounds__(256, 1)
void gemm_relu(float* __restrict__ out, int M) {
    __shared__ unsigned As[2][ABUF];   // 2 x 10 KB
    __shared__ unsigned Bs[2][BBUF];   // 2 x 20 KB

    const int tid  = threadIdx.x;
    const int warp = tid >> 5;
    const int lane = tid & 31;
    const int wm = warp & 1;
    const int wn = warp >> 1;
    const int warpRow = wm * 64;
    const int warpCol = wn * 64;
    const int blockRow = blockIdx.y * BM;
    const int blockCol = blockIdx.x * BN;

    const uint32_t as0 = (uint32_t)__cvta_generic_to_shared(&As[0][0]);
    const uint32_t bs0 = (uint32_t)__cvta_generic_to_shared(&Bs[0][0]);

    float c[4][8][4];
#pragma unroll
    for (int i = 0; i < 4; i++)
#pragma unroll
        for (int j = 0; j < 8; j++)
#pragma unroll
            for (int q = 0; q < 4; q++) c[i][j][q] = 0.f;

    // Async copy of tile kt into buffer b (6 x 16B per thread).
    auto copyTile = [&](int kt, int b) {
        const uint32_t asb = as0 + (uint32_t)b * (ABUF * 4u);
        const uint32_t bsb = bs0 + (uint32_t)b * (BBUF * 4u);
#pragma unroll
        for (int wch = 0; wch < 2; wch++) {
            int idx = tid + wch * 256;
            int ra = idx >> 2, ca = idx & 3;
            int grow = blockRow + ra;
            int sz = (grow < M) ? 16 : 0;
            cp_async16(asb + (uint32_t)(ra * HS + ca * 4) * 4u,
                       g_agg_h + (size_t)grow * ROW_U4 + kt * 4 + ca, sz);
        }
#pragma unroll
        for (int wch = 0; wch < 4; wch++) {
            int idx = tid + wch * 256;
            int rb = idx >> 2, cb = idx & 3;
            cp_async16(bsb + (uint32_t)(rb * HS + cb * 4) * 4u,
                       g_wt_h + (size_t)(blockCol + rb) * (D / 8) + kt * 4 + cb,
                       16);
        }
        cp_commit();
    };

    const int a_row16 = lane & 15;
    const int a_khi   = (lane >> 4) << 2;
    const int b_row8  = lane & 7;
    const int b_jhi   = lane >> 4;
    const int b_khi   = ((lane >> 3) & 1) << 2;

    const int KT = D / BK;  // 16
    copyTile(0, 0);

    for (int kt = 0; kt < KT; kt++) {
        cp_wait0();                       // tile kt landed in buffer kt&1
        __syncthreads();                  // visible to all warps
        if (kt + 1 < KT) copyTile(kt + 1, (kt + 1) & 1);  // async under compute

        const int b = kt & 1;
        const uint32_t asb = as0 + (uint32_t)b * (ABUF * 4u);
        const uint32_t bsb = bs0 + (uint32_t)b * (BBUF * 4u);

#pragma unroll
        for (int ks = 0; ks < 2; ks++) {
            unsigned af[4][4], bf[8][2];
#pragma unroll
            for (int i = 0; i < 4; i++) {
                uint32_t addr = asb +
                    (((warpRow + i * 16 + a_row16) * HS) + ks * 8 + a_khi) * 4u;
                ldsm_x4(af[i][0], af[i][1], af[i][2], af[i][3], addr);
            }
#pragma unroll
            for (int jj = 0; jj < 4; jj++) {
                int j = jj * 2;
                uint32_t addr = bsb +
                    (((warpCol + (j + b_jhi) * 8 + b_row8) * HS) + ks * 8 + b_khi) * 4u;
                ldsm_x4(bf[j][0], bf[j][1], bf[j + 1][0], bf[j + 1][1], addr);
            }
#pragma unroll
            for (int i = 0; i < 4; i++)
#pragma unroll
                for (int j = 0; j < 8; j++) {
                    asm volatile(
                        "mma.sync.aligned.m16n8k16.row.col.f32.f16.f16.f32 "
                        "{%0,%1,%2,%3}, {%4,%5,%6,%7}, {%8,%9}, {%0,%1,%2,%3};"
                        : "+f"(c[i][j][0]), "+f"(c[i][j][1]),
                          "+f"(c[i][j][2]), "+f"(c[i][j][3])
                        : "r"(af[i][0]), "r"(af[i][1]),
                          "r"(af[i][2]), "r"(af[i][3]),
                          "r"(bf[j][0]), "r"(bf[j][1]));
                }
        }
        __syncthreads();   // all warps done reading buffer kt&1 before overwrite
    }

    // Epilogue: ReLU + store
#pragma unroll
    for (int i = 0; i < 4; i++) {
        int r0 = blockRow + warpRow + i * 16 + (lane >> 2);
        int r1 = r0 + 8;
#pragma unroll
        for (int j = 0; j < 8; j++) {
            int col = blockCol + warpCol + j * 8 + (lane & 3) * 2;
            if (r0 < M) {
                float2 v;
                v.x = fmaxf(c[i][j][0], 0.f);
                v.y = fmaxf(c[i][j][1], 0.f);
                *reinterpret_cast<float2*>(out + (size_t)r0 * D + col) = v;
            }
            if (r1 < M) {
                float2 v;
                v.x = fmaxf(c[i][j][2], 0.f);
                v.y = fmaxf(c[i][j][3], 0.f);
                *reinterpret_cast<float2*>(out + (size_t)r1 * D + col) = v;
            }
        }
    }
}

// ---------------------------------------------------------------------------
// kernel_launch: fork-join preprocessing, serial gather -> gemm (R10 topology).
// ---------------------------------------------------------------------------
extern "C" void kernel_launch(void* const* d_in, const int* in_sizes, int n_in,
                              void* d_out, int out_size) {
    const float* h  = (const float*)d_in[0];
    const float* Wt = (const float*)d_in[1];
    const float* ew = (const float*)d_in[2];
    const void* src = d_in[3];
    const void* dst = d_in[4];
    float* out = (float*)d_out;

    int M = in_sizes[0] / D;
    int E = in_sizes[2];

    static cudaStream_t s2 = nullptr;
    static cudaEvent_t evFork = nullptr, evJoin = nullptr;
    if (s2 == nullptr) {
        cudaStreamCreateWithFlags(&s2, cudaStreamNonBlocking);
        cudaEventCreateWithFlags(&evFork, cudaEventDisableTiming);
        cudaEventCreateWithFlags(&evJoin, cudaEventDisableTiming);
    }

    detect_idx_dtype<<<1, 1>>>((const unsigned*)src);

    // fork: CSR chain on s2, fp16 conversions on the capture stream
    cudaEventRecord(evFork, 0);
    cudaStreamWaitEvent(s2, evFork, 0);

    zero_cnt<<<(M + 255) / 256, 256, 0, s2>>>(M);
    hist_dst<<<(E + 255) / 256, 256, 0, s2>>>(dst, E);
    int sblocks = (M + SCAN_TILE - 1) / SCAN_TILE;
    scan_phase1<<<sblocks, SCAN_TILE, 0, s2>>>(M);
    scan_phase2<<<1, 32, 0, s2>>>(sblocks);
    scan_phase3<<<sblocks, SCAN_TILE, 0, s2>>>(M, E);
    reorder_edges<<<(E + 255) / 256, 256, 0, s2>>>(src, dst, ew, E);
    cudaEventRecord(evJoin, s2);

    convert_h<<<2048, 256>>>(h, (long long)M * ROW_U4);
    transpose_w_h<<<dim3(16, 16), dim3(32, 32)>>>(Wt);

    // join
    cudaStreamWaitEvent(0, evJoin, 0);

    long long gthreads = (long long)M * 32;
    gather_agg<<<(int)((gthreads + 255) / 256), 256>>>(M);

    dim3 grid(D / BN, (M + BM - 1) / BM);
    gemm_relu<<<grid, 256>>>(out, M);
}

// round 15
// speedup vs baseline: 1.4223x; 1.4223x over previous
#include <cuda_runtime.h>
#include <cuda_fp16.h>
#include <cstdint>

#define D 512
#define ROW_U4 64         // uint4 per fp16 row (512*2B/16B)
#define MAX_NODES 100000
#define MAX_E 2000000
#define SCAN_TILE 1024
#define MAX_SCAN_BLOCKS 128

// fp16 copies (uint4-typed for alignment)
__device__ uint4 g_h2[(size_t)MAX_NODES * ROW_U4];     // h in fp16
__device__ uint4 g_agg_h[(size_t)MAX_NODES * ROW_U4];  // agg in fp16 (GEMM A)
__device__ uint4 g_wt_h[(size_t)D * D / 8];            // W^T fp16 [N][K]
__device__ int g_is64;
// CSR-by-dst structures
__device__ int   g_cnt[MAX_NODES];
__device__ int   g_off[MAX_NODES + 1];
__device__ int   g_cur[MAX_NODES];
__device__ int2  g_edge[MAX_E];   // (src, edge_weight bits) combined
__device__ int   g_bsum[MAX_SCAN_BLOCKS];

// Bit-cast helpers
__device__ __forceinline__ unsigned h2_to_u(__half2 h) {
    return *reinterpret_cast<unsigned*>(&h);
}
__device__ __forceinline__ __half2 u_to_h2(unsigned u) {
    return *reinterpret_cast<__half2*>(&u);
}
__device__ __forceinline__ void ldsm_x4(unsigned& r0, unsigned& r1,
                                        unsigned& r2, unsigned& r3,
                                        uint32_t addr) {
    asm volatile(
        "ldmatrix.sync.aligned.m8n8.x4.shared.b16 {%0,%1,%2,%3}, [%4];"
        : "=r"(r0), "=r"(r1), "=r"(r2), "=r"(r3) : "r"(addr));
}

// ---------------------------------------------------------------------------
__global__ void detect_idx_dtype(const unsigned* __restrict__ src_words) {
    int all_zero = 1;
    for (int i = 1; i < 64; i += 2)
        if (src_words[i] != 0u) all_zero = 0;
    g_is64 = all_zero;
}

__global__ void convert_h(const float* __restrict__ h, long long n_u4) {
    long long i = blockIdx.x * (long long)blockDim.x + threadIdx.x;
    long long stride = gridDim.x * (long long)blockDim.x;
    for (; i < n_u4; i += stride) {
        const float4* p = reinterpret_cast<const float4*>(h + i * 8);
        float4 v0 = p[0], v1 = p[1];
        uint4 o;
        o.x = h2_to_u(__floats2half2_rn(v0.x, v0.y));
        o.y = h2_to_u(__floats2half2_rn(v0.z, v0.w));
        o.z = h2_to_u(__floats2half2_rn(v1.x, v1.y));
        o.w = h2_to_u(__floats2half2_rn(v1.z, v1.w));
        g_h2[i] = o;
    }
}

__global__ void transpose_w_h(const float* __restrict__ W) {
    __shared__ float t[32][33];
    int bx = blockIdx.x * 32, by = blockIdx.y * 32;
    t[threadIdx.y][threadIdx.x] = W[(by + threadIdx.y) * D + bx + threadIdx.x];
    __syncthreads();
    __half* wt = reinterpret_cast<__half*>(g_wt_h);
    wt[(size_t)(bx + threadIdx.y) * D + by + threadIdx.x] =
        __float2half_rn(t[threadIdx.x][threadIdx.y]);
}

__global__ void zero_cnt(int M) {
    int i = blockIdx.x * blockDim.x + threadIdx.x;
    if (i < M) g_cnt[i] = 0;
}

__global__ void hist_dst(const void* __restrict__ dst_raw, int E) {
    int e = blockIdx.x * blockDim.x + threadIdx.x;
    if (e >= E) return;
    int d = g_is64 ? (int)reinterpret_cast<const long long*>(dst_raw)[e]
                   : reinterpret_cast<const int*>(dst_raw)[e];
    atomicAdd(&g_cnt[d], 1);
}

__global__ void scan_phase1(int M) {
    __shared__ int wsum[32];
    const int tid = threadIdx.x, lane = tid & 31, wid = tid >> 5;
    const int gi = blockIdx.x * SCAN_TILE + tid;

    int x = (gi < M) ? g_cnt[gi] : 0;

    int v = x;
#pragma unroll
    for (int d = 1; d < 32; d <<= 1) {
        int t = __shfl_up_sync(0xffffffffu, v, d);
        if (lane >= d) v += t;
    }
    if (lane == 31) wsum[wid] = v;
    __syncthreads();
    if (wid == 0) {
        int w = wsum[lane];
#pragma unroll
        for (int d = 1; d < 32; d <<= 1) {
            int t = __shfl_up_sync(0xffffffffu, w, d);
            if (lane >= d) w += t;
        }
        wsum[lane] = w;
    }
    __syncthreads();

    int excl = (v - x) + (wid > 0 ? wsum[wid - 1] : 0);
    if (gi < M) g_off[gi] = excl;
    if (tid == SCAN_TILE - 1) g_bsum[blockIdx.x] = excl + x;
}

__global__ void scan_phase2(int nblocks) {
    const int lane = threadIdx.x;
    int run = 0;
    for (int base = 0; base < nblocks; base += 32) {
        int i = base + lane;
        int x = (i < nblocks) ? g_bsum[i] : 0;
        int v = x;
#pragma unroll
        for (int d = 1; d < 32; d <<= 1) {
            int t = __shfl_up_sync(0xffffffffu, v, d);
            if (lane >= d) v += t;
        }
        if (i < nblocks) g_bsum[i] = run + (v - x);
        run += __shfl_sync(0xffffffffu, v, 31);
    }
}

__global__ void scan_phase3(int M, int E) {
    const int gi = blockIdx.x * SCAN_TILE + threadIdx.x;
    if (gi < M) {
        int o = g_off[gi] + g_bsum[blockIdx.x];
        g_off[gi] = o;
        g_cur[gi] = o;
    }
    if (gi == 0) g_off[M] = E;
}

__global__ void reorder_edges(const void* __restrict__ src_raw,
                              const void* __restrict__ dst_raw,
                              const float* __restrict__ ew, int E) {
    int e = blockIdx.x * blockDim.x + threadIdx.x;
    if (e >= E) return;
    int s, d;
    if (g_is64) {
        s = (int)reinterpret_cast<const long long*>(src_raw)[e];
        d = (int)reinterpret_cast<const long long*>(dst_raw)[e];
    } else {
        s = reinterpret_cast<const int*>(src_raw)[e];
        d = reinterpret_cast<const int*>(dst_raw)[e];
    }
    int pos = atomicAdd(&g_cur[d], 1);
    g_edge[pos] = make_int2(s, __float_as_int(ew[e]));
}

// ---------------------------------------------------------------------------
// Gather (fp16 rows): one warp per dst node, 4-edge unroll (16 LDG in flight).
// ---------------------------------------------------------------------------
__device__ __forceinline__ void acc_u4(float2* acc, uint4 q, float w, int base) {
    float2 f;
    f = __half22float2(u_to_h2(q.x));
    acc[base + 0].x += f.x * w; acc[base + 0].y += f.y * w;
    f = __half22float2(u_to_h2(q.y));
    acc[base + 1].x += f.x * w; acc[base + 1].y += f.y * w;
    f = __half22float2(u_to_h2(q.z));
    acc[base + 2].x += f.x * w; acc[base + 2].y += f.y * w;
    f = __half22float2(u_to_h2(q.w));
    acc[base + 3].x += f.x * w; acc[base + 3].y += f.y * w;
}

__global__ void gather_agg(int M) {
    int node = (int)((blockIdx.x * (unsigned)blockDim.x + threadIdx.x) >> 5);
    if (node >= M) return;
    const int lane = threadIdx.x & 31;
    const int beg = g_off[node];
    const int end = g_off[node + 1];

    float2 acc[8];
#pragma unroll
    for (int i = 0; i < 8; i++) acc[i] = make_float2(0.f, 0.f);

    int e = beg;
    for (; e + 3 < end; e += 4) {
        int2 e0 = g_edge[e],     e1 = g_edge[e + 1];
        int2 e2 = g_edge[e + 2], e3 = g_edge[e + 3];
        float w0 = __int_as_float(e0.y), w1 = __int_as_float(e1.y);
        float w2 = __int_as_float(e2.y), w3 = __int_as_float(e3.y);
        const uint4* p0 = g_h2 + (size_t)e0.x * ROW_U4 + lane * 2;
        const uint4* p1 = g_h2 + (size_t)e1.x * ROW_U4 + lane * 2;
        const uint4* p2 = g_h2 + (size_t)e2.x * ROW_U4 + lane * 2;
        const uint4* p3 = g_h2 + (size_t)e3.x * ROW_U4 + lane * 2;
        uint4 q00 = p0[0], q01 = p0[1];
        uint4 q10 = p1[0], q11 = p1[1];
        uint4 q20 = p2[0], q21 = p2[1];
        uint4 q30 = p3[0], q31 = p3[1];
        acc_u4(acc, q00, w0, 0); acc_u4(acc, q01, w0, 4);
        acc_u4(acc, q10, w1, 0); acc_u4(acc, q11, w1, 4);
        acc_u4(acc, q20, w2, 0); acc_u4(acc, q21, w2, 4);
        acc_u4(acc, q30, w3, 0); acc_u4(acc, q31, w3, 4);
    }
    for (; e < end; e++) {
        int2 e0 = g_edge[e];
        float w0 = __int_as_float(e0.y);
        const uint4* p0 = g_h2 + (size_t)e0.x * ROW_U4 + lane * 2;
        uint4 q00 = p0[0], q01 = p0[1];
        acc_u4(acc, q00, w0, 0); acc_u4(acc, q01, w0, 4);
    }

    uint4 o0, o1;
    o0.x = h2_to_u(__floats2half2_rn(acc[0].x, acc[0].y));
    o0.y = h2_to_u(__floats2half2_rn(acc[1].x, acc[1].y));
    o0.z = h2_to_u(__floats2half2_rn(acc[2].x, acc[2].y));
    o0.w = h2_to_u(__floats2half2_rn(acc[3].x, acc[3].y));
    o1.x = h2_to_u(__floats2half2_rn(acc[4].x, acc[4].y));
    o1.y = h2_to_u(__floats2half2_rn(acc[5].x, acc[5].y));
    o1.z = h2_to_u(__floats2half2_rn(acc[6].x, acc[6].y));
    o1.w = h2_to_u(__floats2half2_rn(acc[7].x, acc[7].y));
    uint4* o = g_agg_h + (size_t)node * ROW_U4 + lane * 2;
    o[0] = o0; o[1] = o1;
}

// ---------------------------------------------------------------------------
// fp16 mma.sync GEMM, DOUBLE-BUFFERED smem, register-staged prefetch
// (exact R10 version — the 447.6us best).
// ---------------------------------------------------------------------------
#define BM 128
#define BN 256
#define BK 32
#define HS 20   // half2 stride per row
#define ABUF (BM * HS)
#define BBUF (BN * HS)

__global__ __launch_bounds__(256, 1)
void gemm_relu(float* __restrict__ out, int M) {
    __shared__ unsigned As[2][ABUF];   // 2 x 10 KB
    __shared__ unsigned Bs[2][BBUF];   // 2 x 20 KB

    const int tid  = threadIdx.x;
    const int warp = tid >> 5;
    const int lane = tid & 31;
    const int wm = warp & 1;
    const int wn = warp >> 1;
    const int warpRow = wm * 64;
    const int warpCol = wn * 64;
    const int blockRow = blockIdx.y * BM;
    const int blockCol = blockIdx.x * BN;

    const uint32_t as0 = (uint32_t)__cvta_generic_to_shared(&As[0][0]);
    const uint32_t bs0 = (uint32_t)__cvta_generic_to_shared(&Bs[0][0]);

    float c[4][8][4];
#pragma unroll
    for (int i = 0; i < 4; i++)
#pragma unroll
        for (int j = 0; j < 8; j++)
#pragma unroll
            for (int q = 0; q < 4; q++) c[i][j][q] = 0.f;

    uint4 aReg[2], bReg[4];

    auto loadTile = [&](int kt) {
#pragma unroll
        for (int wch = 0; wch < 2; wch++) {
            int idx = tid + wch * 256;
            int ra = idx >> 2, ca = idx & 3;
            int grow = blockRow + ra;
            if (grow < M)
                aReg[wch] = g_agg_h[(size_t)grow * ROW_U4 + kt * 4 + ca];
            else
                aReg[wch] = make_uint4(0u, 0u, 0u, 0u);
        }
#pragma unroll
        for (int wch = 0; wch < 4; wch++) {
            int idx = tid + wch * 256;
            int rb = idx >> 2, cb = idx & 3;
            bReg[wch] = g_wt_h[(size_t)(blockCol + rb) * (D / 8) + kt * 4 + cb];
        }
    };
    auto storeTile = [&](int b) {
#pragma unroll
        for (int wch = 0; wch < 2; wch++) {
            int idx = tid + wch * 256;
            int ra = idx >> 2, ca = idx & 3;
            unsigned* da = &As[b][ra * HS + ca * 4];
            uint4 v = aReg[wch];
            da[0] = v.x; da[1] = v.y; da[2] = v.z; da[3] = v.w;
        }
#pragma unroll
        for (int wch = 0; wch < 4; wch++) {
            int idx = tid + wch * 256;
            int rb = idx >> 2, cb = idx & 3;
            unsigned* db = &Bs[b][rb * HS + cb * 4];
            uint4 u = bReg[wch];
            db[0] = u.x; db[1] = u.y; db[2] = u.z; db[3] = u.w;
        }
    };

    const int a_row16 = lane & 15;
    const int a_khi   = (lane >> 4) << 2;
    const int b_row8  = lane & 7;
    const int b_jhi   = lane >> 4;
    const int b_khi   = ((lane >> 3) & 1) << 2;

    const int KT = D / BK;  // 16
    loadTile(0);
    storeTile(0);

    for (int kt = 0; kt < KT; kt++) {
        __syncthreads();                 // buffer kt&1 ready for all warps
        if (kt + 1 < KT) loadTile(kt + 1);   // LDG in flight under compute

        const int b = kt & 1;
        const uint32_t asb = as0 + (uint32_t)b * (ABUF * 4u);
        const uint32_t bsb = bs0 + (uint32_t)b * (BBUF * 4u);

#pragma unroll
        for (int ks = 0; ks < 2; ks++) {
            unsigned af[4][4], bf[8][2];
#pragma unroll
            for (int i = 0; i < 4; i++) {
                uint32_t addr = asb +
                    (((warpRow + i * 16 + a_row16) * HS) + ks * 8 + a_khi) * 4u;
                ldsm_x4(af[i][0], af[i][1], af[i][2], af[i][3], addr);
            }
#pragma unroll
            for (int jj = 0; jj < 4; jj++) {
                int j = jj * 2;
                uint32_t addr = bsb +
                    (((warpCol + (j + b_jhi) * 8 + b_row8) * HS) + ks * 8 + b_khi) * 4u;
                ldsm_x4(bf[j][0], bf[j][1], bf[j + 1][0], bf[j + 1][1], addr);
            }
#pragma unroll
            for (int i = 0; i < 4; i++)
#pragma unroll
                for (int j = 0; j < 8; j++) {
                    asm volatile(
                        "mma.sync.aligned.m16n8k16.row.col.f32.f16.f16.f32 "
                        "{%0,%1,%2,%3}, {%4,%5,%6,%7}, {%8,%9}, {%0,%1,%2,%3};"
                        : "+f"(c[i][j][0]), "+f"(c[i][j][1]),
                          "+f"(c[i][j][2]), "+f"(c[i][j][3])
                        : "r"(af[i][0]), "r"(af[i][1]),
                          "r"(af[i][2]), "r"(af[i][3]),
                          "r"(bf[j][0]), "r"(bf[j][1]));
                }
        }
        if (kt + 1 < KT) storeTile((kt + 1) & 1);  // other buffer: no race
    }

    // Epilogue: ReLU + store
#pragma unroll
    for (int i = 0; i < 4; i++) {
        int r0 = blockRow + warpRow + i * 16 + (lane >> 2);
        int r1 = r0 + 8;
#pragma unroll
        for (int j = 0; j < 8; j++) {
            int col = blockCol + warpCol + j * 8 + (lane & 3) * 2;
            if (r0 < M) {
                float2 v;
                v.x = fmaxf(c[i][j][0], 0.f);
                v.y = fmaxf(c[i][j][1], 0.f);
                *reinterpret_cast<float2*>(out + (size_t)r0 * D + col) = v;
            }
            if (r1 < M) {
                float2 v;
                v.x = fmaxf(c[i][j][2], 0.f);
                v.y = fmaxf(c[i][j][3], 0.f);
                *reinterpret_cast<float2*>(out + (size_t)r1 * D + col) = v;
            }
        }
    }
}

// ---------------------------------------------------------------------------
// kernel_launch: fork-join preprocessing, serial gather -> gemm (R10 topology).
// ---------------------------------------------------------------------------
extern "C" void kernel_launch(void* const* d_in, const int* in_sizes, int n_in,
                              void* d_out, int out_size) {
    const float* h  = (const float*)d_in[0];
    const float* Wt = (const float*)d_in[1];
    const float* ew = (const float*)d_in[2];
    const void* src = d_in[3];
    const void* dst = d_in[4];
    float* out = (float*)d_out;

    int M = in_sizes[0] / D;
    int E = in_sizes[2];

    static cudaStream_t s2 = nullptr;
    static cudaEvent_t evFork = nullptr, evJoin = nullptr;
    if (s2 == nullptr) {
        cudaStreamCreateWithFlags(&s2, cudaStreamNonBlocking);
        cudaEventCreateWithFlags(&evFork, cudaEventDisableTiming);
        cudaEventCreateWithFlags(&evJoin, cudaEventDisableTiming);
    }

    detect_idx_dtype<<<1, 1>>>((const unsigned*)src);

    // fork: CSR chain on s2, fp16 conversions on the capture stream
    cudaEventRecord(evFork, 0);
    cudaStreamWaitEvent(s2, evFork, 0);

    zero_cnt<<<(M + 255) / 256, 256, 0, s2>>>(M);
    hist_dst<<<(E + 255) / 256, 256, 0, s2>>>(dst, E);
    int sblocks = (M + SCAN_TILE - 1) / SCAN_TILE;
    scan_phase1<<<sblocks, SCAN_TILE, 0, s2>>>(M);
    scan_phase2<<<1, 32, 0, s2>>>(sblocks);
    scan_phase3<<<sblocks, SCAN_TILE, 0, s2>>>(M, E);
    reorder_edges<<<(E + 255) / 256, 256, 0, s2>>>(src, dst, ew, E);
    cudaEventRecord(evJoin, s2);

    convert_h<<<2048, 256>>>(h, (long long)M * ROW_U4);
    transpose_w_h<<<dim3(16, 16), dim3(32, 32)>>>(Wt);

    // join
    cudaStreamWaitEvent(0, evJoin, 0);

    long long gthreads = (long long)M * 32;
    gather_agg<<<(int)((gthreads + 255) / 256), 256>>>(M);

    dim3 grid(D / BN, (M + BM - 1) / BM);
    gemm_relu<<<grid, 256>>>(out, M);
}